// round 15
// baseline (speedup 1.0000x reference)
#include <cuda_runtime.h>
#include <cuda_fp16.h>
#include <cstdint>
#include <math.h>

#define D_MODEL 1024
#define D_FF    4096
#define N_EXP   8
#define T_TOK   4096
#define CAP     4096
#define SPLITK  4

// SMEM stage geometry (bytes) — tile 128x128, BK=32, 4 stages (proven config)
#define A_ROW_B  80
#define A_PLANE  (128 * A_ROW_B)           // 10240
#define B_ROW_B  272
#define B_PLANE  (32 * B_ROW_B)            // 8704
#define OFF_B    A_PLANE
#define STAGE_B  (A_PLANE + B_PLANE)       // 18944
#define NSTAGE   4
#define HDR_OFF  (NSTAGE * STAGE_B)        // 75776
#define SMEM_TOTAL (HDR_OFF + 1024)        // 76800  (2 CTAs/SM)

#define ROUTER_BLOCKS (T_TOK / 8)          // 512
#define CONV_BLOCKS   4096

// ---------------- scratch (device globals; zero-initialized) ----------------
__device__ int    g_counts[N_EXP];
__device__ int    g_token_list[N_EXP * CAP];
__device__ float  g_gate_slot[N_EXP * CAP];
__device__ __half g_xh[(size_t)T_TOK * D_MODEL];
__device__ __half g_w1[(size_t)N_EXP * D_MODEL * D_FF];
__device__ __half g_w2[(size_t)N_EXP * D_FF * D_MODEL];
__device__ __half g_hh[(size_t)N_EXP * CAP * D_FF];   // rows >= count stay 0

// ---------------- PTX helpers ------------------------------------------------
__device__ __forceinline__ uint32_t smem_u32(const void* p) {
    uint32_t a;
    asm("{ .reg .u64 t; cvta.to.shared.u64 t, %1; cvt.u32.u64 %0, t; }" : "=r"(a) : "l"(p));
    return a;
}
__device__ __forceinline__ void cp16(uint32_t dst, const void* src, int szr) {
    asm volatile("cp.async.cg.shared.global [%0], [%1], 16, %2;"
                 :: "r"(dst), "l"(src), "r"(szr) : "memory");
}
__device__ __forceinline__ void cp_commit() {
    asm volatile("cp.async.commit_group;" ::: "memory");
}
template <int N>
__device__ __forceinline__ void cp_wait() {
    asm volatile("cp.async.wait_group %0;" :: "n"(N) : "memory");
}
__device__ __forceinline__ void ldsm4(uint32_t* r, uint32_t addr) {
    asm volatile("ldmatrix.sync.aligned.m8n8.x4.shared.b16 {%0,%1,%2,%3}, [%4];"
                 : "=r"(r[0]), "=r"(r[1]), "=r"(r[2]), "=r"(r[3]) : "r"(addr));
}
__device__ __forceinline__ void ldsm4t(uint32_t* r, uint32_t addr) {
    asm volatile("ldmatrix.sync.aligned.m8n8.x4.trans.shared.b16 {%0,%1,%2,%3}, [%4];"
                 : "=r"(r[0]), "=r"(r[1]), "=r"(r[2]), "=r"(r[3]) : "r"(addr));
}
__device__ __forceinline__ void mma16816(float* c, const uint32_t* a, const uint32_t* b) {
    asm volatile(
        "mma.sync.aligned.m16n8k16.row.col.f32.f16.f16.f32 "
        "{%0,%1,%2,%3}, {%4,%5,%6,%7}, {%8,%9}, {%0,%1,%2,%3};"
        : "+f"(c[0]), "+f"(c[1]), "+f"(c[2]), "+f"(c[3])
        : "r"(a[0]), "r"(a[1]), "r"(a[2]), "r"(a[3]), "r"(b[0]), "r"(b[1]));
}
__device__ __forceinline__ void red_add_v2(float* addr, float v0, float v1) {
    asm volatile("red.global.add.v2.f32 [%0], {%1, %2};"
                 :: "l"(addr), "f"(v0), "f"(v1) : "memory");
}

// ---------------- small kernels -----------------------------------------------
__global__ void zero_counts_kernel() {
    if (threadIdx.x < N_EXP) g_counts[threadIdx.x] = 0;
}

// ---------------- fused prep: router + x/W1 conversions + out zeroing ----------
__global__ __launch_bounds__(256)
void prep_kernel(const float* __restrict__ x, const float* __restrict__ Wr,
                 const float* __restrict__ br, const float* __restrict__ W1,
                 float* __restrict__ out) {
    if (blockIdx.x < ROUTER_BLOCKS) {
        const int tid = threadIdx.x;
        const int lane = tid & 31;
        const int t = blockIdx.x * 8 + (tid >> 5);

        float acc[N_EXP];
#pragma unroll
        for (int e = 0; e < N_EXP; e++) acc[e] = 0.f;
        const float* xr = x + (size_t)t * D_MODEL;
        for (int d = lane; d < D_MODEL; d += 32) {
            float xv = xr[d];
            const float* w = Wr + (size_t)d * N_EXP;
#pragma unroll
            for (int e = 0; e < N_EXP; e++) acc[e] += xv * w[e];
        }
#pragma unroll
        for (int off = 16; off > 0; off >>= 1)
#pragma unroll
            for (int e = 0; e < N_EXP; e++)
                acc[e] += __shfl_down_sync(0xffffffffu, acc[e], off);
        if (lane != 0) return;

        float p[N_EXP], mx = -1e30f, den = 0.f;
#pragma unroll
        for (int e = 0; e < N_EXP; e++) { p[e] = acc[e] + br[e]; mx = fmaxf(mx, p[e]); }
#pragma unroll
        for (int e = 0; e < N_EXP; e++) { p[e] = expf(p[e] - mx); den += p[e]; }
#pragma unroll
        for (int e = 0; e < N_EXP; e++) p[e] /= den;

        int e0 = 0;
#pragma unroll
        for (int e = 1; e < N_EXP; e++) if (p[e] > p[e0]) e0 = e;
        int e1 = (e0 == 0) ? 1 : 0;
#pragma unroll
        for (int e = 0; e < N_EXP; e++) { if (e == e0) continue; if (p[e] > p[e1]) e1 = e; }
        float s = p[e0] + p[e1];

        int i0 = atomicAdd(&g_counts[e0], 1);
        int i1 = atomicAdd(&g_counts[e1], 1);
        g_token_list[e0 * CAP + i0] = t;
        g_token_list[e1 * CAP + i1] = t;
        g_gate_slot[e0 * CAP + i0] = p[e0] / s;
        g_gate_slot[e1 * CAP + i1] = p[e1] / s;
    } else {
        const size_t n4x = (size_t)T_TOK * D_MODEL / 4;
        const size_t n4w = (size_t)N_EXP * D_MODEL * D_FF / 4;
        const size_t n4o = (size_t)T_TOK * D_MODEL / 4;
        const size_t b0 = n4x, b1 = n4x + n4w;
        const size_t total = b1 + n4o;
        const size_t stride = (size_t)CONV_BLOCKS * 256;
        size_t i = (size_t)(blockIdx.x - ROUTER_BLOCKS) * 256 + threadIdx.x;
        for (; i < total; i += stride) {
            if (i < b0) {
                float4 v = ((const float4*)x)[i];
                ((__half2*)g_xh)[2 * i]     = __floats2half2_rn(v.x, v.y);
                ((__half2*)g_xh)[2 * i + 1] = __floats2half2_rn(v.z, v.w);
            } else if (i < b1) {
                size_t j = i - b0;
                float4 v = ((const float4*)W1)[j];
                ((__half2*)g_w1)[2 * j]     = __floats2half2_rn(v.x, v.y);
                ((__half2*)g_w1)[2 * j + 1] = __floats2half2_rn(v.z, v.w);
            } else {
                ((float4*)out)[i - b1] = make_float4(0.f, 0.f, 0.f, 0.f);
            }
        }
    }
}

// ---------------- GEMM compute step: warp tile 64x64, warp grid 2x2 ------------
__device__ __forceinline__ void compute_stage(uint32_t sb, uint32_t soff,
                                              int wm, int wn, int lane,
                                              float acc[4][8][4]) {
    const uint32_t lrow = lane & 15;
    const uint32_t lhi  = (lane >> 4) << 3;
#pragma unroll
    for (int ks = 0; ks < 2; ks++) {
        uint32_t a[4][4];
#pragma unroll
        for (int mt = 0; mt < 4; mt++) {
            uint32_t addr = sb + soff
                + (uint32_t)(wm * 64 + mt * 16 + lrow) * A_ROW_B
                + (ks * 16 + lhi) * 2;
            ldsm4(a[mt], addr);
        }
        uint32_t b[8][2];
#pragma unroll
        for (int nt2 = 0; nt2 < 4; nt2++) {
            uint32_t addr = sb + soff + OFF_B
                + (uint32_t)(ks * 16 + lrow) * B_ROW_B
                + (uint32_t)(wn * 64 + nt2 * 16 + lhi) * 2;
            uint32_t t[4];
            ldsm4t(t, addr);
            b[nt2 * 2][0] = t[0];     b[nt2 * 2][1] = t[1];
            b[nt2 * 2 + 1][0] = t[2]; b[nt2 * 2 + 1][1] = t[3];
        }
#pragma unroll
        for (int mt = 0; mt < 4; mt++)
#pragma unroll
            for (int nt = 0; nt < 8; nt++)
                mma16816(acc[mt][nt], a[mt], b[nt]);
    }
}

// ---------------- GEMM1 (+ hidden W2 conversion plane) -------------------------
__global__ __launch_bounds__(128, 2)
void gemm1_mma(const float* __restrict__ b1, const float* __restrict__ W2) {
    if (blockIdx.z == N_EXP) {
        const size_t n4w = (size_t)N_EXP * D_FF * D_MODEL / 4;
        const size_t nblk = (size_t)gridDim.x * gridDim.y;
        const size_t stride = nblk * 128;
        size_t i = (size_t)(blockIdx.y * gridDim.x + blockIdx.x) * 128 + threadIdx.x;
        for (; i < n4w; i += stride) {
            float4 v = ((const float4*)W2)[i];
            ((__half2*)g_w2)[2 * i]     = __floats2half2_rn(v.x, v.y);
            ((__half2*)g_w2)[2 * i + 1] = __floats2half2_rn(v.z, v.w);
        }
        return;
    }

    extern __shared__ char smem[];
    const int e = blockIdx.z;
    const int count = g_counts[e];
    const int m0 = blockIdx.y * 128;
    if (m0 >= count) return;
    const int n0 = blockIdx.x * 128;

    const int tid = threadIdx.x;
    const int lane = tid & 31, wid = tid >> 5;
    const int wm = wid >> 1, wn = wid & 1;
    const uint32_t sb = smem_u32(smem);

    int* stok = (int*)(smem + HDR_OFF);
    int* ssz  = (int*)(smem + HDR_OFF + 512);
    {
        int r = m0 + tid;
        bool v = r < count;
        stok[tid] = v ? g_token_list[e * CAP + r] : 0;
        ssz[tid]  = v ? 16 : 0;
    }
    __syncthreads();

    const __half* Bg = g_w1 + (size_t)e * D_MODEL * D_FF;

    auto issue_loads = [&](int stage, int k0) {
#pragma unroll
        for (int h = 0; h < 4; h++) {
            int idx = tid + h * 128;
            int row = idx >> 2, c4 = idx & 3;
            uint32_t dst = sb + stage * STAGE_B + (uint32_t)row * A_ROW_B + c4 * 16;
            cp16(dst, g_xh + (size_t)stok[row] * D_MODEL + k0 + c4 * 8, ssz[row]);
        }
#pragma unroll
        for (int h = 0; h < 4; h++) {
            int idx = tid + h * 128;
            int row = idx >> 4, c16 = idx & 15;
            uint32_t dst = sb + stage * STAGE_B + OFF_B
                         + (uint32_t)row * B_ROW_B + c16 * 16;
            cp16(dst, Bg + (size_t)(k0 + row) * D_FF + n0 + c16 * 8, 16);
        }
        cp_commit();
    };

    float acc[4][8][4];
#pragma unroll
    for (int mt = 0; mt < 4; mt++)
#pragma unroll
        for (int nt = 0; nt < 8; nt++)
#pragma unroll
            for (int q = 0; q < 4; q++) acc[mt][nt][q] = 0.f;

    const int NCH = D_MODEL / 32;  // 32
    issue_loads(0, 0);
    issue_loads(1, 32);
    issue_loads(2, 64);

#pragma unroll 1
    for (int i = 0; i < NCH; i++) {
        cp_wait<2>();
        __syncthreads();
        if (i + 3 < NCH) issue_loads((i + 3) & 3, (i + 3) * 32);
        else cp_commit();
        compute_stage(sb, (i & 3) * STAGE_B, wm, wn, lane, acc);
    }

    // epilogue: bias + relu -> fp16 plane
    const int lrow = lane >> 2, lcol = (lane & 3) * 2;
    const float* b1e = b1 + (size_t)e * D_FF + n0 + wn * 64;
    float2 bias[8];
#pragma unroll
    for (int nt = 0; nt < 8; nt++) bias[nt] = *(const float2*)(b1e + nt * 8 + lcol);

#pragma unroll
    for (int mt = 0; mt < 4; mt++)
#pragma unroll
        for (int half = 0; half < 2; half++) {
            int r = m0 + wm * 64 + mt * 16 + lrow + half * 8;
            if (r >= count) continue;
            size_t base = ((size_t)e * CAP + r) * D_FF + n0 + wn * 64;
#pragma unroll
            for (int nt = 0; nt < 8; nt++) {
                float v0 = fmaxf(acc[mt][nt][half * 2 + 0] + bias[nt].x, 0.f);
                float v1 = fmaxf(acc[mt][nt][half * 2 + 1] + bias[nt].y, 0.f);
                *(__half2*)(g_hh + base + nt * 8 + lcol) = __floats2half2_rn(v0, v1);
            }
        }
}

// ---------------- GEMM2 (split-K=4): out[tok] += gate*(h @ W2[e] + b2[e]) ------
__global__ __launch_bounds__(128, 2)
void gemm2_mma(const float* __restrict__ b2, float* __restrict__ out) {
    extern __shared__ char smem[];
    const int e = blockIdx.z >> 2;
    const int split = blockIdx.z & 3;
    const int count = g_counts[e];
    const int m0 = blockIdx.y * 128;
    if (m0 >= count) return;
    const int n0 = blockIdx.x * 128;
    const int kbase = split * (D_FF / SPLITK);

    const int tid = threadIdx.x;
    const int lane = tid & 31, wid = tid >> 5;
    const int wm = wid >> 1, wn = wid & 1;
    const uint32_t sb = smem_u32(smem);

    const __half* Bg = g_w2 + (size_t)e * D_FF * D_MODEL;
    const size_t arow0 = ((size_t)e * CAP + m0) * D_FF + kbase;

    auto issue_loads = [&](int stage, int k0) {
#pragma unroll
        for (int h = 0; h < 4; h++) {
            int idx = tid + h * 128;
            int row = idx >> 2, c4 = idx & 3;
            uint32_t dst = sb + stage * STAGE_B + (uint32_t)row * A_ROW_B + c4 * 16;
            cp16(dst, g_hh + arow0 + (size_t)row * D_FF + k0 + c4 * 8, 16);
        }
#pragma unroll
        for (int h = 0; h < 4; h++) {
            int idx = tid + h * 128;
            int row = idx >> 4, c16 = idx & 15;
            uint32_t dst = sb + stage * STAGE_B + OFF_B
                         + (uint32_t)row * B_ROW_B + c16 * 16;
            cp16(dst, Bg + (size_t)(kbase + k0 + row) * D_MODEL + n0 + c16 * 8, 16);
        }
        cp_commit();
    };

    float acc[4][8][4];
#pragma unroll
    for (int mt = 0; mt < 4; mt++)
#pragma unroll
        for (int nt = 0; nt < 8; nt++)
#pragma unroll
            for (int q = 0; q < 4; q++) acc[mt][nt][q] = 0.f;

    const int NCH = (D_FF / SPLITK) / 32;  // 32
    issue_loads(0, 0);
    issue_loads(1, 32);
    issue_loads(2, 64);

#pragma unroll 1
    for (int i = 0; i < NCH; i++) {
        cp_wait<2>();
        __syncthreads();
        if (i + 3 < NCH) issue_loads((i + 3) & 3, (i + 3) * 32);
        else cp_commit();
        compute_stage(sb, (i & 3) * STAGE_B, wm, wn, lane, acc);
    }

    // epilogue: (bias only from split 0) + gate, vectorized v2 reductions
    const int lrow = lane >> 2, lcol = (lane & 3) * 2;
    const float* b2e = b2 + (size_t)e * D_MODEL + n0 + wn * 64;
    float2 bias[8];
#pragma unroll
    for (int nt = 0; nt < 8; nt++) {
        if (split == 0) bias[nt] = *(const float2*)(b2e + nt * 8 + lcol);
        else            bias[nt] = make_float2(0.f, 0.f);
    }

#pragma unroll
    for (int mt = 0; mt < 4; mt++)
#pragma unroll
        for (int half = 0; half < 2; half++) {
            int r = m0 + wm * 64 + mt * 16 + lrow + half * 8;
            if (r >= count) continue;
            int tok = g_token_list[e * CAP + r];
            float gate = g_gate_slot[e * CAP + r];
            float* op = out + (size_t)tok * D_MODEL + n0 + wn * 64;
#pragma unroll
            for (int nt = 0; nt < 8; nt++) {
                red_add_v2(op + nt * 8 + lcol,
                           (acc[mt][nt][half * 2 + 0] + bias[nt].x) * gate,
                           (acc[mt][nt][half * 2 + 1] + bias[nt].y) * gate);
            }
        }
}

// ---------------- launch --------------------------------------------------------
extern "C" void kernel_launch(void* const* d_in, const int* in_sizes, int n_in,
                              void* d_out, int out_size) {
    const float* x  = (const float*)d_in[0];
    const float* Wr = (const float*)d_in[1];
    const float* br = (const float*)d_in[2];
    const float* W1 = (const float*)d_in[3];
    const float* b1 = (const float*)d_in[4];
    const float* W2 = (const float*)d_in[5];
    const float* b2 = (const float*)d_in[6];
    float* out = (float*)d_out;

    cudaFuncSetAttribute(gemm1_mma, cudaFuncAttributeMaxDynamicSharedMemorySize, SMEM_TOTAL);
    cudaFuncSetAttribute(gemm2_mma, cudaFuncAttributeMaxDynamicSharedMemorySize, SMEM_TOTAL);

    zero_counts_kernel<<<1, 32>>>();

    prep_kernel<<<ROUTER_BLOCKS + CONV_BLOCKS, 256>>>(x, Wr, br, W1, out);

    dim3 g1(D_FF / 128, CAP / 128, N_EXP + 1);
    gemm1_mma<<<g1, 128, SMEM_TOTAL>>>(b1, W2);

    dim3 g2(D_MODEL / 128, CAP / 128, N_EXP * SPLITK);
    gemm2_mma<<<g2, 128, SMEM_TOTAL>>>(b2, out);
}

// round 16
// speedup vs baseline: 1.0145x; 1.0145x over previous
#include <cuda_runtime.h>
#include <cuda_fp16.h>
#include <cstdint>
#include <math.h>

#define D_MODEL 1024
#define D_FF    4096
#define N_EXP   8
#define T_TOK   4096
#define CAP     4096

// SMEM stage geometry (bytes) — tile 128x128, BK=32, 5 stages
#define A_ROW_B  80
#define A_PLANE  (128 * A_ROW_B)           // 10240
#define B_ROW_B  272
#define B_PLANE  (32 * B_ROW_B)            // 8704
#define OFF_B    A_PLANE
#define STAGE_B  (A_PLANE + B_PLANE)       // 18944
#define NSTAGE   5
#define HDR_OFF  (NSTAGE * STAGE_B)        // 94720
#define SMEM_TOTAL (HDR_OFF + 1024)        // 95744  (2 CTAs/SM: 191.5 KB)

#define ROUTER_BLOCKS (T_TOK / 8)          // 512
#define CONV_BLOCKS   4096

// ---------------- scratch (device globals; zero-initialized) ----------------
__device__ int    g_counts[N_EXP];
__device__ int    g_token_list[N_EXP * CAP];
__device__ float  g_gate_slot[N_EXP * CAP];
__device__ __half g_xh[(size_t)T_TOK * D_MODEL];
__device__ __half g_w1[(size_t)N_EXP * D_MODEL * D_FF];
__device__ __half g_w2[(size_t)N_EXP * D_FF * D_MODEL];
__device__ __half g_hh[(size_t)N_EXP * CAP * D_FF];   // rows >= count stay 0

// ---------------- PTX helpers ------------------------------------------------
__device__ __forceinline__ uint32_t smem_u32(const void* p) {
    uint32_t a;
    asm("{ .reg .u64 t; cvta.to.shared.u64 t, %1; cvt.u32.u64 %0, t; }" : "=r"(a) : "l"(p));
    return a;
}
__device__ __forceinline__ void cp16(uint32_t dst, const void* src, int szr) {
    asm volatile("cp.async.cg.shared.global [%0], [%1], 16, %2;"
                 :: "r"(dst), "l"(src), "r"(szr) : "memory");
}
__device__ __forceinline__ void cp_commit() {
    asm volatile("cp.async.commit_group;" ::: "memory");
}
template <int N>
__device__ __forceinline__ void cp_wait() {
    asm volatile("cp.async.wait_group %0;" :: "n"(N) : "memory");
}
__device__ __forceinline__ void ldsm4(uint32_t* r, uint32_t addr) {
    asm volatile("ldmatrix.sync.aligned.m8n8.x4.shared.b16 {%0,%1,%2,%3}, [%4];"
                 : "=r"(r[0]), "=r"(r[1]), "=r"(r[2]), "=r"(r[3]) : "r"(addr));
}
__device__ __forceinline__ void ldsm4t(uint32_t* r, uint32_t addr) {
    asm volatile("ldmatrix.sync.aligned.m8n8.x4.trans.shared.b16 {%0,%1,%2,%3}, [%4];"
                 : "=r"(r[0]), "=r"(r[1]), "=r"(r[2]), "=r"(r[3]) : "r"(addr));
}
__device__ __forceinline__ void mma16816(float* c, const uint32_t* a, const uint32_t* b) {
    asm volatile(
        "mma.sync.aligned.m16n8k16.row.col.f32.f16.f16.f32 "
        "{%0,%1,%2,%3}, {%4,%5,%6,%7}, {%8,%9}, {%0,%1,%2,%3};"
        : "+f"(c[0]), "+f"(c[1]), "+f"(c[2]), "+f"(c[3])
        : "r"(a[0]), "r"(a[1]), "r"(a[2]), "r"(a[3]), "r"(b[0]), "r"(b[1]));
}
__device__ __forceinline__ void red_add_v2(float* addr, float v0, float v1) {
    asm volatile("red.global.add.v2.f32 [%0], {%1, %2};"
                 :: "l"(addr), "f"(v0), "f"(v1) : "memory");
}

// ---------------- small kernels -----------------------------------------------
__global__ void zero_counts_kernel() {
    if (threadIdx.x < N_EXP) g_counts[threadIdx.x] = 0;
}

// ---------------- fused prep: router + x/W1 conversions + out zeroing ----------
__global__ __launch_bounds__(256)
void prep_kernel(const float* __restrict__ x, const float* __restrict__ Wr,
                 const float* __restrict__ br, const float* __restrict__ W1,
                 float* __restrict__ out) {
    if (blockIdx.x < ROUTER_BLOCKS) {
        const int tid = threadIdx.x;
        const int lane = tid & 31;
        const int t = blockIdx.x * 8 + (tid >> 5);

        float acc[N_EXP];
#pragma unroll
        for (int e = 0; e < N_EXP; e++) acc[e] = 0.f;
        const float* xr = x + (size_t)t * D_MODEL;
        for (int d = lane; d < D_MODEL; d += 32) {
            float xv = xr[d];
            const float* w = Wr + (size_t)d * N_EXP;
#pragma unroll
            for (int e = 0; e < N_EXP; e++) acc[e] += xv * w[e];
        }
#pragma unroll
        for (int off = 16; off > 0; off >>= 1)
#pragma unroll
            for (int e = 0; e < N_EXP; e++)
                acc[e] += __shfl_down_sync(0xffffffffu, acc[e], off);
        if (lane != 0) return;

        float p[N_EXP], mx = -1e30f, den = 0.f;
#pragma unroll
        for (int e = 0; e < N_EXP; e++) { p[e] = acc[e] + br[e]; mx = fmaxf(mx, p[e]); }
#pragma unroll
        for (int e = 0; e < N_EXP; e++) { p[e] = expf(p[e] - mx); den += p[e]; }
#pragma unroll
        for (int e = 0; e < N_EXP; e++) p[e] /= den;

        int e0 = 0;
#pragma unroll
        for (int e = 1; e < N_EXP; e++) if (p[e] > p[e0]) e0 = e;
        int e1 = (e0 == 0) ? 1 : 0;
#pragma unroll
        for (int e = 0; e < N_EXP; e++) { if (e == e0) continue; if (p[e] > p[e1]) e1 = e; }
        float s = p[e0] + p[e1];

        int i0 = atomicAdd(&g_counts[e0], 1);
        int i1 = atomicAdd(&g_counts[e1], 1);
        g_token_list[e0 * CAP + i0] = t;
        g_token_list[e1 * CAP + i1] = t;
        g_gate_slot[e0 * CAP + i0] = p[e0] / s;
        g_gate_slot[e1 * CAP + i1] = p[e1] / s;
    } else {
        const size_t n4x = (size_t)T_TOK * D_MODEL / 4;
        const size_t n4w = (size_t)N_EXP * D_MODEL * D_FF / 4;
        const size_t n4o = (size_t)T_TOK * D_MODEL / 4;
        const size_t b0 = n4x, b1 = n4x + n4w;
        const size_t total = b1 + n4o;
        const size_t stride = (size_t)CONV_BLOCKS * 256;
        size_t i = (size_t)(blockIdx.x - ROUTER_BLOCKS) * 256 + threadIdx.x;
        for (; i < total; i += stride) {
            if (i < b0) {
                float4 v = ((const float4*)x)[i];
                ((__half2*)g_xh)[2 * i]     = __floats2half2_rn(v.x, v.y);
                ((__half2*)g_xh)[2 * i + 1] = __floats2half2_rn(v.z, v.w);
            } else if (i < b1) {
                size_t j = i - b0;
                float4 v = ((const float4*)W1)[j];
                ((__half2*)g_w1)[2 * j]     = __floats2half2_rn(v.x, v.y);
                ((__half2*)g_w1)[2 * j + 1] = __floats2half2_rn(v.z, v.w);
            } else {
                ((float4*)out)[i - b1] = make_float4(0.f, 0.f, 0.f, 0.f);
            }
        }
    }
}

// ---------------- GEMM compute step: warp tile 64x64, warp grid 2x2 ------------
__device__ __forceinline__ void compute_stage(uint32_t sb, uint32_t soff,
                                              int wm, int wn, int lane,
                                              float acc[4][8][4]) {
    const uint32_t lrow = lane & 15;
    const uint32_t lhi  = (lane >> 4) << 3;
#pragma unroll
    for (int ks = 0; ks < 2; ks++) {
        uint32_t a[4][4];
#pragma unroll
        for (int mt = 0; mt < 4; mt++) {
            uint32_t addr = sb + soff
                + (uint32_t)(wm * 64 + mt * 16 + lrow) * A_ROW_B
                + (ks * 16 + lhi) * 2;
            ldsm4(a[mt], addr);
        }
        uint32_t b[8][2];
#pragma unroll
        for (int nt2 = 0; nt2 < 4; nt2++) {
            uint32_t addr = sb + soff + OFF_B
                + (uint32_t)(ks * 16 + lrow) * B_ROW_B
                + (uint32_t)(wn * 64 + nt2 * 16 + lhi) * 2;
            uint32_t t[4];
            ldsm4t(t, addr);
            b[nt2 * 2][0] = t[0];     b[nt2 * 2][1] = t[1];
            b[nt2 * 2 + 1][0] = t[2]; b[nt2 * 2 + 1][1] = t[3];
        }
#pragma unroll
        for (int mt = 0; mt < 4; mt++)
#pragma unroll
            for (int nt = 0; nt < 8; nt++)
                mma16816(acc[mt][nt], a[mt], b[nt]);
    }
}

// ---------------- GEMM1 (+ hidden W2 conversion plane) -------------------------
__global__ __launch_bounds__(128, 2)
void gemm1_mma(const float* __restrict__ b1, const float* __restrict__ W2) {
    if (blockIdx.z == N_EXP) {
        const size_t n4w = (size_t)N_EXP * D_FF * D_MODEL / 4;
        const size_t nblk = (size_t)gridDim.x * gridDim.y;
        const size_t stride = nblk * 128;
        size_t i = (size_t)(blockIdx.y * gridDim.x + blockIdx.x) * 128 + threadIdx.x;
        for (; i < n4w; i += stride) {
            float4 v = ((const float4*)W2)[i];
            ((__half2*)g_w2)[2 * i]     = __floats2half2_rn(v.x, v.y);
            ((__half2*)g_w2)[2 * i + 1] = __floats2half2_rn(v.z, v.w);
        }
        return;
    }

    extern __shared__ char smem[];
    const int e = blockIdx.z;
    const int count = g_counts[e];
    const int m0 = blockIdx.y * 128;
    if (m0 >= count) return;
    const int n0 = blockIdx.x * 128;

    const int tid = threadIdx.x;
    const int lane = tid & 31, wid = tid >> 5;
    const int wm = wid >> 1, wn = wid & 1;
    const uint32_t sb = smem_u32(smem);

    int* stok = (int*)(smem + HDR_OFF);
    int* ssz  = (int*)(smem + HDR_OFF + 512);
    {
        int r = m0 + tid;
        bool v = r < count;
        stok[tid] = v ? g_token_list[e * CAP + r] : 0;
        ssz[tid]  = v ? 16 : 0;
    }
    __syncthreads();

    const __half* Bg = g_w1 + (size_t)e * D_MODEL * D_FF;

    auto issue_loads = [&](int stage, int k0) {
#pragma unroll
        for (int h = 0; h < 4; h++) {
            int idx = tid + h * 128;
            int row = idx >> 2, c4 = idx & 3;
            uint32_t dst = sb + stage * STAGE_B + (uint32_t)row * A_ROW_B + c4 * 16;
            cp16(dst, g_xh + (size_t)stok[row] * D_MODEL + k0 + c4 * 8, ssz[row]);
        }
#pragma unroll
        for (int h = 0; h < 4; h++) {
            int idx = tid + h * 128;
            int row = idx >> 4, c16 = idx & 15;
            uint32_t dst = sb + stage * STAGE_B + OFF_B
                         + (uint32_t)row * B_ROW_B + c16 * 16;
            cp16(dst, Bg + (size_t)(k0 + row) * D_FF + n0 + c16 * 8, 16);
        }
        cp_commit();
    };

    float acc[4][8][4];
#pragma unroll
    for (int mt = 0; mt < 4; mt++)
#pragma unroll
        for (int nt = 0; nt < 8; nt++)
#pragma unroll
            for (int q = 0; q < 4; q++) acc[mt][nt][q] = 0.f;

    const int NCH = D_MODEL / 32;  // 32
    issue_loads(0, 0);
    issue_loads(1, 32);
    issue_loads(2, 64);
    issue_loads(3, 96);

    int cur = 0, nxt = 4;
#pragma unroll 1
    for (int i = 0; i < NCH; i++) {
        cp_wait<3>();
        __syncthreads();
        if (i + 4 < NCH) {
            issue_loads(nxt, (i + 4) * 32);
        } else cp_commit();
        compute_stage(sb, cur * STAGE_B, wm, wn, lane, acc);
        if (++cur == NSTAGE) cur = 0;
        if (++nxt == NSTAGE) nxt = 0;
    }

    // epilogue: bias + relu -> fp16 plane
    const int lrow = lane >> 2, lcol = (lane & 3) * 2;
    const float* b1e = b1 + (size_t)e * D_FF + n0 + wn * 64;
    float2 bias[8];
#pragma unroll
    for (int nt = 0; nt < 8; nt++) bias[nt] = *(const float2*)(b1e + nt * 8 + lcol);

#pragma unroll
    for (int mt = 0; mt < 4; mt++)
#pragma unroll
        for (int half = 0; half < 2; half++) {
            int r = m0 + wm * 64 + mt * 16 + lrow + half * 8;
            if (r >= count) continue;
            size_t base = ((size_t)e * CAP + r) * D_FF + n0 + wn * 64;
#pragma unroll
            for (int nt = 0; nt < 8; nt++) {
                float v0 = fmaxf(acc[mt][nt][half * 2 + 0] + bias[nt].x, 0.f);
                float v1 = fmaxf(acc[mt][nt][half * 2 + 1] + bias[nt].y, 0.f);
                *(__half2*)(g_hh + base + nt * 8 + lcol) = __floats2half2_rn(v0, v1);
            }
        }
}

// ---------------- GEMM2 (split-K=2): out[tok] += gate*(h @ W2[e] + b2[e]) ------
__global__ __launch_bounds__(128, 2)
void gemm2_mma(const float* __restrict__ b2, float* __restrict__ out) {
    extern __shared__ char smem[];
    const int e = blockIdx.z >> 1;
    const int split = blockIdx.z & 1;
    const int count = g_counts[e];
    const int m0 = blockIdx.y * 128;
    if (m0 >= count) return;
    const int n0 = blockIdx.x * 128;
    const int kbase = split * (D_FF / 2);

    const int tid = threadIdx.x;
    const int lane = tid & 31, wid = tid >> 5;
    const int wm = wid >> 1, wn = wid & 1;
    const uint32_t sb = smem_u32(smem);

    const __half* Bg = g_w2 + (size_t)e * D_FF * D_MODEL;
    const size_t arow0 = ((size_t)e * CAP + m0) * D_FF + kbase;

    auto issue_loads = [&](int stage, int k0) {
#pragma unroll
        for (int h = 0; h < 4; h++) {
            int idx = tid + h * 128;
            int row = idx >> 2, c4 = idx & 3;
            uint32_t dst = sb + stage * STAGE_B + (uint32_t)row * A_ROW_B + c4 * 16;
            cp16(dst, g_hh + arow0 + (size_t)row * D_FF + k0 + c4 * 8, 16);
        }
#pragma unroll
        for (int h = 0; h < 4; h++) {
            int idx = tid + h * 128;
            int row = idx >> 4, c16 = idx & 15;
            uint32_t dst = sb + stage * STAGE_B + OFF_B
                         + (uint32_t)row * B_ROW_B + c16 * 16;
            cp16(dst, Bg + (size_t)(kbase + k0 + row) * D_MODEL + n0 + c16 * 8, 16);
        }
        cp_commit();
    };

    float acc[4][8][4];
#pragma unroll
    for (int mt = 0; mt < 4; mt++)
#pragma unroll
        for (int nt = 0; nt < 8; nt++)
#pragma unroll
            for (int q = 0; q < 4; q++) acc[mt][nt][q] = 0.f;

    const int NCH = (D_FF / 2) / 32;  // 64
    issue_loads(0, 0);
    issue_loads(1, 32);
    issue_loads(2, 64);
    issue_loads(3, 96);

    int cur = 0, nxt = 4;
#pragma unroll 1
    for (int i = 0; i < NCH; i++) {
        cp_wait<3>();
        __syncthreads();
        if (i + 4 < NCH) {
            issue_loads(nxt, (i + 4) * 32);
        } else cp_commit();
        compute_stage(sb, cur * STAGE_B, wm, wn, lane, acc);
        if (++cur == NSTAGE) cur = 0;
        if (++nxt == NSTAGE) nxt = 0;
    }

    // epilogue: (bias only from split 0) + gate, vectorized v2 reductions
    const int lrow = lane >> 2, lcol = (lane & 3) * 2;
    const float* b2e = b2 + (size_t)e * D_MODEL + n0 + wn * 64;
    float2 bias[8];
#pragma unroll
    for (int nt = 0; nt < 8; nt++) {
        if (split == 0) bias[nt] = *(const float2*)(b2e + nt * 8 + lcol);
        else            bias[nt] = make_float2(0.f, 0.f);
    }

#pragma unroll
    for (int mt = 0; mt < 4; mt++)
#pragma unroll
        for (int half = 0; half < 2; half++) {
            int r = m0 + wm * 64 + mt * 16 + lrow + half * 8;
            if (r >= count) continue;
            int tok = g_token_list[e * CAP + r];
            float gate = g_gate_slot[e * CAP + r];
            float* op = out + (size_t)tok * D_MODEL + n0 + wn * 64;
#pragma unroll
            for (int nt = 0; nt < 8; nt++) {
                red_add_v2(op + nt * 8 + lcol,
                           (acc[mt][nt][half * 2 + 0] + bias[nt].x) * gate,
                           (acc[mt][nt][half * 2 + 1] + bias[nt].y) * gate);
            }
        }
}

// ---------------- launch --------------------------------------------------------
extern "C" void kernel_launch(void* const* d_in, const int* in_sizes, int n_in,
                              void* d_out, int out_size) {
    const float* x  = (const float*)d_in[0];
    const float* Wr = (const float*)d_in[1];
    const float* br = (const float*)d_in[2];
    const float* W1 = (const float*)d_in[3];
    const float* b1 = (const float*)d_in[4];
    const float* W2 = (const float*)d_in[5];
    const float* b2 = (const float*)d_in[6];
    float* out = (float*)d_out;

    cudaFuncSetAttribute(gemm1_mma, cudaFuncAttributeMaxDynamicSharedMemorySize, SMEM_TOTAL);
    cudaFuncSetAttribute(gemm2_mma, cudaFuncAttributeMaxDynamicSharedMemorySize, SMEM_TOTAL);

    zero_counts_kernel<<<1, 32>>>();

    prep_kernel<<<ROUTER_BLOCKS + CONV_BLOCKS, 256>>>(x, Wr, br, W1, out);

    dim3 g1(D_FF / 128, CAP / 128, N_EXP + 1);
    gemm1_mma<<<g1, 128, SMEM_TOTAL>>>(b1, W2);

    dim3 g2(D_MODEL / 128, CAP / 128, N_EXP * 2);
    gemm2_mma<<<g2, 128, SMEM_TOTAL>>>(b2, out);
}

// round 17
// speedup vs baseline: 1.0341x; 1.0193x over previous
#include <cuda_runtime.h>
#include <cuda_fp16.h>
#include <cstdint>
#include <math.h>

#define D_MODEL 1024
#define D_FF    4096
#define N_EXP   8
#define T_TOK   4096
#define CAP     4096

// SMEM stage geometry (bytes) — tile 128x128, BK=32, 4 stages (measured best)
#define A_ROW_B  80
#define A_PLANE  (128 * A_ROW_B)           // 10240
#define B_ROW_B  272
#define B_PLANE  (32 * B_ROW_B)            // 8704
#define OFF_B    A_PLANE
#define STAGE_B  (A_PLANE + B_PLANE)       // 18944
#define NSTAGE   4
#define HDR_OFF  (NSTAGE * STAGE_B)        // 75776
#define SMEM_TOTAL (HDR_OFF + 1024)        // 76800  (2 CTAs/SM: 153.6 KB)

#define ROUTER_BLOCKS (T_TOK / 8)          // 512
#define CONV_BLOCKS   4096

// ---------------- scratch (device globals; zero-initialized) ----------------
__device__ int    g_counts[N_EXP];
__device__ int    g_token_list[N_EXP * CAP];
__device__ float  g_gate_slot[N_EXP * CAP];
__device__ __half g_xh[(size_t)T_TOK * D_MODEL];
__device__ __half g_w1[(size_t)N_EXP * D_MODEL * D_FF];
__device__ __half g_w2[(size_t)N_EXP * D_FF * D_MODEL];
__device__ __half g_hh[(size_t)N_EXP * CAP * D_FF];   // rows >= count stay 0

// ---------------- PTX helpers ------------------------------------------------
__device__ __forceinline__ uint32_t smem_u32(const void* p) {
    uint32_t a;
    asm("{ .reg .u64 t; cvta.to.shared.u64 t, %1; cvt.u32.u64 %0, t; }" : "=r"(a) : "l"(p));
    return a;
}
__device__ __forceinline__ void cp16(uint32_t dst, const void* src, int szr) {
    asm volatile("cp.async.cg.shared.global [%0], [%1], 16, %2;"
                 :: "r"(dst), "l"(src), "r"(szr) : "memory");
}
__device__ __forceinline__ void cp_commit() {
    asm volatile("cp.async.commit_group;" ::: "memory");
}
template <int N>
__device__ __forceinline__ void cp_wait() {
    asm volatile("cp.async.wait_group %0;" :: "n"(N) : "memory");
}
__device__ __forceinline__ void ldsm4(uint32_t* r, uint32_t addr) {
    asm volatile("ldmatrix.sync.aligned.m8n8.x4.shared.b16 {%0,%1,%2,%3}, [%4];"
                 : "=r"(r[0]), "=r"(r[1]), "=r"(r[2]), "=r"(r[3]) : "r"(addr));
}
__device__ __forceinline__ void ldsm4t(uint32_t* r, uint32_t addr) {
    asm volatile("ldmatrix.sync.aligned.m8n8.x4.trans.shared.b16 {%0,%1,%2,%3}, [%4];"
                 : "=r"(r[0]), "=r"(r[1]), "=r"(r[2]), "=r"(r[3]) : "r"(addr));
}
__device__ __forceinline__ void mma16816(float* c, const uint32_t* a, const uint32_t* b) {
    asm volatile(
        "mma.sync.aligned.m16n8k16.row.col.f32.f16.f16.f32 "
        "{%0,%1,%2,%3}, {%4,%5,%6,%7}, {%8,%9}, {%0,%1,%2,%3};"
        : "+f"(c[0]), "+f"(c[1]), "+f"(c[2]), "+f"(c[3])
        : "r"(a[0]), "r"(a[1]), "r"(a[2]), "r"(a[3]), "r"(b[0]), "r"(b[1]));
}
__device__ __forceinline__ void red_add_v2(float* addr, float v0, float v1) {
    asm volatile("red.global.add.v2.f32 [%0], {%1, %2};"
                 :: "l"(addr), "f"(v0), "f"(v1) : "memory");
}

// ---------------- fused prep: router + x/W1 conversions + out zeroing ----------
__global__ __launch_bounds__(256)
void prep_kernel(const float* __restrict__ x, const float* __restrict__ Wr,
                 const float* __restrict__ br, const float* __restrict__ W1,
                 float* __restrict__ out) {
    if (blockIdx.x < ROUTER_BLOCKS) {
        const int tid = threadIdx.x;
        const int lane = tid & 31;
        const int t = blockIdx.x * 8 + (tid >> 5);

        float acc[N_EXP];
#pragma unroll
        for (int e = 0; e < N_EXP; e++) acc[e] = 0.f;
        const float* xr = x + (size_t)t * D_MODEL;
        for (int d = lane; d < D_MODEL; d += 32) {
            float xv = xr[d];
            const float* w = Wr + (size_t)d * N_EXP;
#pragma unroll
            for (int e = 0; e < N_EXP; e++) acc[e] += xv * w[e];
        }
#pragma unroll
        for (int off = 16; off > 0; off >>= 1)
#pragma unroll
            for (int e = 0; e < N_EXP; e++)
                acc[e] += __shfl_down_sync(0xffffffffu, acc[e], off);
        if (lane != 0) return;

        float p[N_EXP], mx = -1e30f, den = 0.f;
#pragma unroll
        for (int e = 0; e < N_EXP; e++) { p[e] = acc[e] + br[e]; mx = fmaxf(mx, p[e]); }
#pragma unroll
        for (int e = 0; e < N_EXP; e++) { p[e] = expf(p[e] - mx); den += p[e]; }
#pragma unroll
        for (int e = 0; e < N_EXP; e++) p[e] /= den;

        int e0 = 0;
#pragma unroll
        for (int e = 1; e < N_EXP; e++) if (p[e] > p[e0]) e0 = e;
        int e1 = (e0 == 0) ? 1 : 0;
#pragma unroll
        for (int e = 0; e < N_EXP; e++) { if (e == e0) continue; if (p[e] > p[e1]) e1 = e; }
        float s = p[e0] + p[e1];

        int i0 = atomicAdd(&g_counts[e0], 1);
        int i1 = atomicAdd(&g_counts[e1], 1);
        g_token_list[e0 * CAP + i0] = t;
        g_token_list[e1 * CAP + i1] = t;
        g_gate_slot[e0 * CAP + i0] = p[e0] / s;
        g_gate_slot[e1 * CAP + i1] = p[e1] / s;
    } else {
        const size_t n4x = (size_t)T_TOK * D_MODEL / 4;
        const size_t n4w = (size_t)N_EXP * D_MODEL * D_FF / 4;
        const size_t n4o = (size_t)T_TOK * D_MODEL / 4;
        const size_t b0 = n4x, b1 = n4x + n4w;
        const size_t total = b1 + n4o;
        const size_t stride = (size_t)CONV_BLOCKS * 256;
        size_t i = (size_t)(blockIdx.x - ROUTER_BLOCKS) * 256 + threadIdx.x;
        for (; i < total; i += stride) {
            if (i < b0) {
                float4 v = ((const float4*)x)[i];
                ((__half2*)g_xh)[2 * i]     = __floats2half2_rn(v.x, v.y);
                ((__half2*)g_xh)[2 * i + 1] = __floats2half2_rn(v.z, v.w);
            } else if (i < b1) {
                size_t j = i - b0;
                float4 v = ((const float4*)W1)[j];
                ((__half2*)g_w1)[2 * j]     = __floats2half2_rn(v.x, v.y);
                ((__half2*)g_w1)[2 * j + 1] = __floats2half2_rn(v.z, v.w);
            } else {
                ((float4*)out)[i - b1] = make_float4(0.f, 0.f, 0.f, 0.f);
            }
        }
    }
}

// ---------------- GEMM compute step: warp tile 64x64, warp grid 2x2 ------------
__device__ __forceinline__ void compute_stage(uint32_t sb, uint32_t soff,
                                              int wm, int wn, int lane,
                                              float acc[4][8][4]) {
    const uint32_t lrow = lane & 15;
    const uint32_t lhi  = (lane >> 4) << 3;
#pragma unroll
    for (int ks = 0; ks < 2; ks++) {
        uint32_t a[4][4];
#pragma unroll
        for (int mt = 0; mt < 4; mt++) {
            uint32_t addr = sb + soff
                + (uint32_t)(wm * 64 + mt * 16 + lrow) * A_ROW_B
                + (ks * 16 + lhi) * 2;
            ldsm4(a[mt], addr);
        }
        uint32_t b[8][2];
#pragma unroll
        for (int nt2 = 0; nt2 < 4; nt2++) {
            uint32_t addr = sb + soff + OFF_B
                + (uint32_t)(ks * 16 + lrow) * B_ROW_B
                + (uint32_t)(wn * 64 + nt2 * 16 + lhi) * 2;
            uint32_t t[4];
            ldsm4t(t, addr);
            b[nt2 * 2][0] = t[0];     b[nt2 * 2][1] = t[1];
            b[nt2 * 2 + 1][0] = t[2]; b[nt2 * 2 + 1][1] = t[3];
        }
#pragma unroll
        for (int mt = 0; mt < 4; mt++)
#pragma unroll
            for (int nt = 0; nt < 8; nt++)
                mma16816(acc[mt][nt], a[mt], b[nt]);
    }
}

// ---------------- GEMM1 (+ hidden W2 conversion plane) -------------------------
__global__ __launch_bounds__(128, 2)
void gemm1_mma(const float* __restrict__ b1, const float* __restrict__ W2) {
    if (blockIdx.z == N_EXP) {
        const size_t n4w = (size_t)N_EXP * D_FF * D_MODEL / 4;
        const size_t nblk = (size_t)gridDim.x * gridDim.y;
        const size_t stride = nblk * 128;
        size_t i = (size_t)(blockIdx.y * gridDim.x + blockIdx.x) * 128 + threadIdx.x;
        for (; i < n4w; i += stride) {
            float4 v = ((const float4*)W2)[i];
            ((__half2*)g_w2)[2 * i]     = __floats2half2_rn(v.x, v.y);
            ((__half2*)g_w2)[2 * i + 1] = __floats2half2_rn(v.z, v.w);
        }
        return;
    }

    extern __shared__ char smem[];
    const int e = blockIdx.z;
    const int count = g_counts[e];
    const int m0 = blockIdx.y * 128;
    if (m0 >= count) return;
    const int n0 = blockIdx.x * 128;

    const int tid = threadIdx.x;
    const int lane = tid & 31, wid = tid >> 5;
    const int wm = wid >> 1, wn = wid & 1;
    const uint32_t sb = smem_u32(smem);

    int* stok = (int*)(smem + HDR_OFF);
    int* ssz  = (int*)(smem + HDR_OFF + 512);
    {
        int r = m0 + tid;
        bool v = r < count;
        stok[tid] = v ? g_token_list[e * CAP + r] : 0;
        ssz[tid]  = v ? 16 : 0;
    }
    __syncthreads();

    const __half* Bg = g_w1 + (size_t)e * D_MODEL * D_FF;

    auto issue_loads = [&](int stage, int k0) {
#pragma unroll
        for (int h = 0; h < 4; h++) {
            int idx = tid + h * 128;
            int row = idx >> 2, c4 = idx & 3;
            uint32_t dst = sb + stage * STAGE_B + (uint32_t)row * A_ROW_B + c4 * 16;
            cp16(dst, g_xh + (size_t)stok[row] * D_MODEL + k0 + c4 * 8, ssz[row]);
        }
#pragma unroll
        for (int h = 0; h < 4; h++) {
            int idx = tid + h * 128;
            int row = idx >> 4, c16 = idx & 15;
            uint32_t dst = sb + stage * STAGE_B + OFF_B
                         + (uint32_t)row * B_ROW_B + c16 * 16;
            cp16(dst, Bg + (size_t)(k0 + row) * D_FF + n0 + c16 * 8, 16);
        }
        cp_commit();
    };

    float acc[4][8][4];
#pragma unroll
    for (int mt = 0; mt < 4; mt++)
#pragma unroll
        for (int nt = 0; nt < 8; nt++)
#pragma unroll
            for (int q = 0; q < 4; q++) acc[mt][nt][q] = 0.f;

    const int NCH = D_MODEL / 32;  // 32
    issue_loads(0, 0);
    issue_loads(1, 32);
    issue_loads(2, 64);

#pragma unroll 1
    for (int i = 0; i < NCH; i++) {
        cp_wait<2>();
        __syncthreads();
        if (i + 3 < NCH) issue_loads((i + 3) & 3, (i + 3) * 32);
        else cp_commit();
        compute_stage(sb, (i & 3) * STAGE_B, wm, wn, lane, acc);
    }

    // epilogue: bias + relu -> fp16 plane
    const int lrow = lane >> 2, lcol = (lane & 3) * 2;
    const float* b1e = b1 + (size_t)e * D_FF + n0 + wn * 64;
    float2 bias[8];
#pragma unroll
    for (int nt = 0; nt < 8; nt++) bias[nt] = *(const float2*)(b1e + nt * 8 + lcol);

#pragma unroll
    for (int mt = 0; mt < 4; mt++)
#pragma unroll
        for (int half = 0; half < 2; half++) {
            int r = m0 + wm * 64 + mt * 16 + lrow + half * 8;
            if (r >= count) continue;
            size_t base = ((size_t)e * CAP + r) * D_FF + n0 + wn * 64;
#pragma unroll
            for (int nt = 0; nt < 8; nt++) {
                float v0 = fmaxf(acc[mt][nt][half * 2 + 0] + bias[nt].x, 0.f);
                float v1 = fmaxf(acc[mt][nt][half * 2 + 1] + bias[nt].y, 0.f);
                *(__half2*)(g_hh + base + nt * 8 + lcol) = __floats2half2_rn(v0, v1);
            }
        }
}

// ---------------- GEMM2 (split-K=2): out[tok] += gate*(h @ W2[e] + b2[e]) ------
__global__ __launch_bounds__(128, 2)
void gemm2_mma(const float* __restrict__ b2, float* __restrict__ out) {
    extern __shared__ char smem[];
    const int e = blockIdx.z >> 1;
    const int split = blockIdx.z & 1;
    const int count = g_counts[e];
    const int m0 = blockIdx.y * 128;
    if (m0 >= count) return;
    const int n0 = blockIdx.x * 128;
    const int kbase = split * (D_FF / 2);

    const int tid = threadIdx.x;
    const int lane = tid & 31, wid = tid >> 5;
    const int wm = wid >> 1, wn = wid & 1;
    const uint32_t sb = smem_u32(smem);

    const __half* Bg = g_w2 + (size_t)e * D_FF * D_MODEL;
    const size_t arow0 = ((size_t)e * CAP + m0) * D_FF + kbase;

    auto issue_loads = [&](int stage, int k0) {
#pragma unroll
        for (int h = 0; h < 4; h++) {
            int idx = tid + h * 128;
            int row = idx >> 2, c4 = idx & 3;
            uint32_t dst = sb + stage * STAGE_B + (uint32_t)row * A_ROW_B + c4 * 16;
            cp16(dst, g_hh + arow0 + (size_t)row * D_FF + k0 + c4 * 8, 16);
        }
#pragma unroll
        for (int h = 0; h < 4; h++) {
            int idx = tid + h * 128;
            int row = idx >> 4, c16 = idx & 15;
            uint32_t dst = sb + stage * STAGE_B + OFF_B
                         + (uint32_t)row * B_ROW_B + c16 * 16;
            cp16(dst, Bg + (size_t)(kbase + k0 + row) * D_MODEL + n0 + c16 * 8, 16);
        }
        cp_commit();
    };

    float acc[4][8][4];
#pragma unroll
    for (int mt = 0; mt < 4; mt++)
#pragma unroll
        for (int nt = 0; nt < 8; nt++)
#pragma unroll
            for (int q = 0; q < 4; q++) acc[mt][nt][q] = 0.f;

    const int NCH = (D_FF / 2) / 32;  // 64
    issue_loads(0, 0);
    issue_loads(1, 32);
    issue_loads(2, 64);

#pragma unroll 1
    for (int i = 0; i < NCH; i++) {
        cp_wait<2>();
        __syncthreads();
        if (i + 3 < NCH) issue_loads((i + 3) & 3, (i + 3) * 32);
        else cp_commit();
        compute_stage(sb, (i & 3) * STAGE_B, wm, wn, lane, acc);
    }

    // epilogue: (bias only from split 0) + gate, vectorized v2 reductions
    const int lrow = lane >> 2, lcol = (lane & 3) * 2;
    const float* b2e = b2 + (size_t)e * D_MODEL + n0 + wn * 64;
    float2 bias[8];
#pragma unroll
    for (int nt = 0; nt < 8; nt++) {
        if (split == 0) bias[nt] = *(const float2*)(b2e + nt * 8 + lcol);
        else            bias[nt] = make_float2(0.f, 0.f);
    }

#pragma unroll
    for (int mt = 0; mt < 4; mt++)
#pragma unroll
        for (int half = 0; half < 2; half++) {
            int r = m0 + wm * 64 + mt * 16 + lrow + half * 8;
            if (r >= count) continue;
            int tok = g_token_list[e * CAP + r];
            float gate = g_gate_slot[e * CAP + r];
            float* op = out + (size_t)tok * D_MODEL + n0 + wn * 64;
#pragma unroll
            for (int nt = 0; nt < 8; nt++) {
                red_add_v2(op + nt * 8 + lcol,
                           (acc[mt][nt][half * 2 + 0] + bias[nt].x) * gate,
                           (acc[mt][nt][half * 2 + 1] + bias[nt].y) * gate);
            }
        }
}

// ---------------- launch --------------------------------------------------------
extern "C" void kernel_launch(void* const* d_in, const int* in_sizes, int n_in,
                              void* d_out, int out_size) {
    const float* x  = (const float*)d_in[0];
    const float* Wr = (const float*)d_in[1];
    const float* br = (const float*)d_in[2];
    const float* W1 = (const float*)d_in[3];
    const float* b1 = (const float*)d_in[4];
    const float* W2 = (const float*)d_in[5];
    const float* b2 = (const float*)d_in[6];
    float* out = (float*)d_out;

    cudaFuncSetAttribute(gemm1_mma, cudaFuncAttributeMaxDynamicSharedMemorySize, SMEM_TOTAL);
    cudaFuncSetAttribute(gemm2_mma, cudaFuncAttributeMaxDynamicSharedMemorySize, SMEM_TOTAL);

    // zero expert counters via async memset (graph-capturable, no extra kernel)
    void* cnt_ptr = nullptr;
    cudaGetSymbolAddress(&cnt_ptr, g_counts);
    cudaMemsetAsync(cnt_ptr, 0, N_EXP * sizeof(int));

    prep_kernel<<<ROUTER_BLOCKS + CONV_BLOCKS, 256>>>(x, Wr, br, W1, out);

    dim3 g1(D_FF / 128, CAP / 128, N_EXP + 1);
    gemm1_mma<<<g1, 128, SMEM_TOTAL>>>(b1, W2);

    dim3 g2(D_MODEL / 128, CAP / 128, N_EXP * 2);
    gemm2_mma<<<g2, 128, SMEM_TOTAL>>>(b2, out);
}